// round 1
// baseline (speedup 1.0000x reference)
#include <cuda_runtime.h>
#include <cuda_bf16.h>
#include <cstdint>

// Problem constants
#define BATCH 32
#define NPTS  8192
#define DIM   128
#define LAM   0.01f

// SYRK tiling
#define SPLITS 8
#define CHUNK  (NPTS / SPLITS)   // 1024 rows per split-CTA
#define KT     32                // rows per smem tile
#define TILES  (CHUNK / KT)      // 32 tiles per CTA

// Static device scratch (no dynamic allocation allowed)
__device__ float g_covp[SPLITS][BATCH][DIM][DIM];  // 16 MB partial sums
__device__ float g_sums[SPLITS][BATCH][DIM];       // partial column sums
__device__ float g_cov[BATCH][DIM][DIM];           // finalized cov before sort

// ---------------------------------------------------------------------------
// Kernel 1: split-K SYRK.  Each CTA handles (batch b, split s): 1024 rows.
// 256 threads, 16x16 layout, each thread computes an 8x8 block of the 128x128
// output. Also accumulates per-column sums (threads 0..127) from the smem tile.
// ---------------------------------------------------------------------------
__global__ __launch_bounds__(256, 2)
void syrk_kernel(const float* __restrict__ x) {
    const int bid = blockIdx.x;         // 0 .. BATCH*SPLITS-1
    const int b = bid / SPLITS;
    const int s = bid % SPLITS;
    const float* __restrict__ xb = x + ((size_t)b * NPTS + (size_t)s * CHUNK) * DIM;

    __shared__ float tileF[KT * DIM];   // 16 KB

    const int tid = threadIdx.x;
    const int ty = tid >> 4;            // 0..15
    const int tx = tid & 15;            // 0..15
    const int row0 = ty * 8;
    const int col0 = tx * 8;

    float acc[8][8];
#pragma unroll
    for (int i = 0; i < 8; ++i)
#pragma unroll
        for (int j = 0; j < 8; ++j) acc[i][j] = 0.f;

    float colsum = 0.f;

    for (int t = 0; t < TILES; ++t) {
        __syncthreads();
        // cooperative tile load: 32 rows x 128 floats = 1024 float4
        const float4* __restrict__ src = (const float4*)(xb + (size_t)t * KT * DIM);
        float4* dst = (float4*)tileF;
#pragma unroll
        for (int r = 0; r < 4; ++r) {
            dst[tid + 256 * r] = src[tid + 256 * r];
        }
        __syncthreads();

        // column sums from smem (threads 0..127 each own one column)
        if (tid < DIM) {
#pragma unroll
            for (int r = 0; r < KT; ++r) colsum += tileF[r * DIM + tid];
        }

        // 8x8 register-blocked outer products over KT k-steps
#pragma unroll 4
        for (int k = 0; k < KT; ++k) {
            const float* rowp = &tileF[k * DIM];
            float4 a0 = *(const float4*)(rowp + row0);
            float4 a1 = *(const float4*)(rowp + row0 + 4);
            float4 b0 = *(const float4*)(rowp + col0);
            float4 b1 = *(const float4*)(rowp + col0 + 4);
            float av[8] = {a0.x, a0.y, a0.z, a0.w, a1.x, a1.y, a1.z, a1.w};
            float bv[8] = {b0.x, b0.y, b0.z, b0.w, b1.x, b1.y, b1.z, b1.w};
#pragma unroll
            for (int i = 0; i < 8; ++i)
#pragma unroll
                for (int j = 0; j < 8; ++j)
                    acc[i][j] = fmaf(av[i], bv[j], acc[i][j]);
        }
    }

    // write partial results (deterministic: each split owns its slab)
    float* outp = &g_covp[s][b][0][0];
#pragma unroll
    for (int i = 0; i < 8; ++i) {
        float4* o = (float4*)(outp + (size_t)(row0 + i) * DIM + col0);
        o[0] = make_float4(acc[i][0], acc[i][1], acc[i][2], acc[i][3]);
        o[1] = make_float4(acc[i][4], acc[i][5], acc[i][6], acc[i][7]);
    }
    if (tid < DIM) g_sums[s][b][tid] = colsum;
}

// ---------------------------------------------------------------------------
// Kernel 2: finalize.  cov = (sum_s covp - N*m*m^T)/(N-1) + LAM*I
// ---------------------------------------------------------------------------
__global__ void finalize_kernel() {
    const int gi = blockIdx.x * blockDim.x + threadIdx.x;  // 0..BATCH*DIM*DIM-1
    if (gi >= BATCH * DIM * DIM) return;
    const int b = gi >> 14;
    const int rem = gi & 16383;
    const int d = rem >> 7;
    const int e = rem & 127;

    float s = 0.f;
#pragma unroll
    for (int sp = 0; sp < SPLITS; ++sp) s += g_covp[sp][b][d][e];

    float sd = 0.f, se = 0.f;
#pragma unroll
    for (int sp = 0; sp < SPLITS; ++sp) { sd += g_sums[sp][b][d]; se += g_sums[sp][b][e]; }
    const float md = sd * (1.0f / NPTS);
    const float me = se * (1.0f / NPTS);

    float v = (s - (float)NPTS * md * me) * (1.0f / (NPTS - 1));
    if (d == e) v += LAM;
    g_cov[b][d][e] = v;
}

// ---------------------------------------------------------------------------
// Kernel 3: lexicographic rank + gather.  One block per batch, 128 threads.
// rank[i] = #{ j : row_j <lex row_i }  (stable tie-break by index; ties are
// measure-zero with generic float data but handled anyway).
// ---------------------------------------------------------------------------
__global__ void sort_kernel(float* __restrict__ out) {
    const int b = blockIdx.x;
    const int i = threadIdx.x;   // 0..127
    __shared__ float key0[DIM];
    __shared__ int   rank[DIM];

    const float* __restrict__ cb = &g_cov[b][0][0];
    key0[i] = cb[(size_t)i * DIM];
    __syncthreads();

    const float ki = key0[i];
    int r = 0;
    for (int j = 0; j < DIM; ++j) {
        const float kj = key0[j];
        if (kj < ki) { ++r; continue; }
        if (kj == ki && j != i) {
            // full lexicographic fallback
            bool decided = false;
            for (int c = 1; c < DIM; ++c) {
                const float aj = cb[(size_t)j * DIM + c];
                const float ai = cb[(size_t)i * DIM + c];
                if (aj != ai) { if (aj < ai) ++r; decided = true; break; }
            }
            if (!decided && j < i) ++r;  // fully equal rows: stable order
        }
    }
    rank[i] = r;
    __syncthreads();

    // gather: row i of cov goes to output row rank[i]
    const float4* __restrict__ srcr = (const float4*)(cb + (size_t)i * DIM);
    float4* dstr = (float4*)(out + (size_t)b * (DIM * DIM) + (size_t)rank[i] * DIM);
#pragma unroll
    for (int c = 0; c < DIM / 4; ++c) dstr[c] = srcr[c];
}

// ---------------------------------------------------------------------------
extern "C" void kernel_launch(void* const* d_in, const int* in_sizes, int n_in,
                              void* d_out, int out_size) {
    const float* x = (const float*)d_in[0];
    float* out = (float*)d_out;

    syrk_kernel<<<BATCH * SPLITS, 256>>>(x);

    const int total = BATCH * DIM * DIM;
    finalize_kernel<<<(total + 255) / 256, 256>>>();

    sort_kernel<<<BATCH, DIM>>>(out);
}

// round 7
// speedup vs baseline: 2.7671x; 2.7671x over previous
#include <cuda_runtime.h>
#include <cuda_bf16.h>
#include <cstdint>

// Problem constants
#define BATCH 32
#define NPTS  8192
#define DIM   128
#define LAM   0.01f

// split-K SYRK config
#define SPLITS 8
#define KC     (NPTS / SPLITS)   // 1024 k-rows per CTA
#define KT     32                // k-rows per smem tile
#define TILES  (KC / KT)         // 32
#define SD     136               // smem row stride (floats)

// Static device scratch
__device__ float g_covp[SPLITS][BATCH][DIM][DIM];  // 16 MB partials
__device__ float g_sums[SPLITS][BATCH][DIM];
__device__ float g_keyp[SPLITS][BATCH][DIM];       // exact fp32 dot(col_d, col_0) partials
__device__ float g_cov[BATCH][DIM][DIM];

// ---------------------------------------------------------------------------
// tf32 warp MMA m16n8k8 — layout VERIFIED (bitwise-matches wmma result)
// ---------------------------------------------------------------------------
__device__ __forceinline__ void mma_tf32(float c[4],
                                         uint32_t a0, uint32_t a1, uint32_t a2, uint32_t a3,
                                         uint32_t b0, uint32_t b1) {
    asm volatile(
        "mma.sync.aligned.m16n8k8.row.col.f32.tf32.tf32.f32 "
        "{%0,%1,%2,%3}, {%4,%5,%6,%7}, {%8,%9}, {%0,%1,%2,%3};"
        : "+f"(c[0]), "+f"(c[1]), "+f"(c[2]), "+f"(c[3])
        : "r"(a0), "r"(a1), "r"(a2), "r"(a3), "r"(b0), "r"(b1));
}

__device__ __forceinline__ uint32_t to_tf32(float v) {
    uint32_t u;
    asm("cvt.rn.tf32.f32 %0, %1;" : "=r"(u) : "f"(v));
    return u;
}

// ---------------------------------------------------------------------------
// Kernel 1: split-K SYRK via tf32 mma.sync + exact fp32 key-column dots.
// grid = BATCH*SPLITS, 256 threads (8 warps).
// ---------------------------------------------------------------------------
__global__ __launch_bounds__(256, 2)
void syrk_mma_kernel(const float* __restrict__ x) {
    __shared__ float  sA[2][KT * SD];
    __shared__ float4 sCsum[256];
    __shared__ float4 sKsum[256];

    const int bid = blockIdx.x;
    const int b = bid / SPLITS;
    const int s = bid % SPLITS;
    const float* __restrict__ xb = x + ((size_t)b * NPTS + (size_t)s * KC) * DIM;

    const int tid  = threadIdx.x;
    const int lane = tid & 31;
    const int wid  = tid >> 5;
    const int g    = lane >> 2;          // group id 0..7
    const int t4   = lane & 3;           // thread-in-group 0..3
    const int wm   = (wid & 3) * 32;     // warp M offset
    const int wn   = (wid >> 2) * 64;    // warp N offset
    const int d4   = tid & 31;           // fixed column group (4 cols) for loads
    const int krow = tid >> 5;           // base k-row within tile for loads

    float4 csum = make_float4(0.f, 0.f, 0.f, 0.f);
    float4 ksum = make_float4(0.f, 0.f, 0.f, 0.f);
    float acc[2][8][4];
#pragma unroll
    for (int mt = 0; mt < 2; ++mt)
#pragma unroll
        for (int nt = 0; nt < 8; ++nt)
#pragma unroll
            for (int q = 0; q < 4; ++q) acc[mt][nt][q] = 0.f;

    float4 pv[4];

    // ---- prologue: load tile 0, convert, store, accumulate sums/keys ----
    {
        const float4* src = (const float4*)xb;
#pragma unroll
        for (int r = 0; r < 4; ++r) pv[r] = __ldg(src + tid + 256 * r);
#pragma unroll
        for (int r = 0; r < 4; ++r) {
            const float x0 = __shfl_sync(0xffffffffu, pv[r].x, 0);
            csum.x += pv[r].x; csum.y += pv[r].y;
            csum.z += pv[r].z; csum.w += pv[r].w;
            ksum.x = fmaf(pv[r].x, x0, ksum.x);
            ksum.y = fmaf(pv[r].y, x0, ksum.y);
            ksum.z = fmaf(pv[r].z, x0, ksum.z);
            ksum.w = fmaf(pv[r].w, x0, ksum.w);
            const int k = krow + 8 * r;
            uint4 uv = make_uint4(to_tf32(pv[r].x), to_tf32(pv[r].y),
                                  to_tf32(pv[r].z), to_tf32(pv[r].w));
            *(uint4*)&sA[0][k * SD + d4 * 4] = uv;
        }
    }
    __syncthreads();

    // ---- main loop ----
    for (int t = 0; t < TILES; ++t) {
        const int cur = t & 1;

        if (t + 1 < TILES) {
            const float4* src = (const float4*)(xb + (size_t)(t + 1) * KT * DIM);
#pragma unroll
            for (int r = 0; r < 4; ++r) pv[r] = __ldg(src + tid + 256 * r);
        }

        // 4 k-steps of 8 over the current 32-row tile
#pragma unroll
        for (int ks = 0; ks < 4; ++ks) {
            const float* base = &sA[cur][(ks * 8 + t4) * SD];

            uint32_t bf[8][2];
#pragma unroll
            for (int nt = 0; nt < 8; ++nt) {
                bf[nt][0] = __float_as_uint(base[wn + nt * 8 + g]);
                bf[nt][1] = __float_as_uint(base[4 * SD + wn + nt * 8 + g]);
            }
#pragma unroll
            for (int mt = 0; mt < 2; ++mt) {
                const int m0 = wm + mt * 16;
                uint32_t a0 = __float_as_uint(base[m0 + g]);
                uint32_t a1 = __float_as_uint(base[m0 + g + 8]);
                uint32_t a2 = __float_as_uint(base[4 * SD + m0 + g]);
                uint32_t a3 = __float_as_uint(base[4 * SD + m0 + g + 8]);
#pragma unroll
                for (int nt = 0; nt < 8; ++nt)
                    mma_tf32(acc[mt][nt], a0, a1, a2, a3, bf[nt][0], bf[nt][1]);
            }
        }

        if (t + 1 < TILES) {
            const int nxt = (t + 1) & 1;
#pragma unroll
            for (int r = 0; r < 4; ++r) {
                const float x0 = __shfl_sync(0xffffffffu, pv[r].x, 0);
                csum.x += pv[r].x; csum.y += pv[r].y;
                csum.z += pv[r].z; csum.w += pv[r].w;
                ksum.x = fmaf(pv[r].x, x0, ksum.x);
                ksum.y = fmaf(pv[r].y, x0, ksum.y);
                ksum.z = fmaf(pv[r].z, x0, ksum.z);
                ksum.w = fmaf(pv[r].w, x0, ksum.w);
                const int k = krow + 8 * r;
                uint4 uv = make_uint4(to_tf32(pv[r].x), to_tf32(pv[r].y),
                                      to_tf32(pv[r].z), to_tf32(pv[r].w));
                *(uint4*)&sA[nxt][k * SD + d4 * 4] = uv;
            }
        }
        __syncthreads();
    }

    // ---- column-sum + key reductions ----
    sCsum[tid] = csum;
    sKsum[tid] = ksum;
    __syncthreads();
    if (tid < 32) {
        float4 a = sCsum[tid];
        float4 k = sKsum[tid];
#pragma unroll
        for (int w = 1; w < 8; ++w) {
            float4 v = sCsum[tid + 32 * w];
            a.x += v.x; a.y += v.y; a.z += v.z; a.w += v.w;
            float4 u = sKsum[tid + 32 * w];
            k.x += u.x; k.y += u.y; k.z += u.z; k.w += u.w;
        }
        ((float4*)&g_sums[s][b][0])[tid] = a;
        ((float4*)&g_keyp[s][b][0])[tid] = k;
    }

    // ---- write partial cov ----
    float* outp = &g_covp[s][b][0][0];
#pragma unroll
    for (int mt = 0; mt < 2; ++mt) {
#pragma unroll
        for (int nt = 0; nt < 8; ++nt) {
            const int row = wm + mt * 16 + g;
            const int col = wn + nt * 8 + t4 * 2;
            *(float2*)&outp[(size_t)row * DIM + col] =
                make_float2(acc[mt][nt][0], acc[mt][nt][1]);
            *(float2*)&outp[(size_t)(row + 8) * DIM + col] =
                make_float2(acc[mt][nt][2], acc[mt][nt][3]);
        }
    }
}

// ---------------------------------------------------------------------------
// Kernel 2: finalize. cov = (sum_s covp - N*m*m^T)/(N-1) + LAM*I.
// Column 0 (the lexsort primary key) is overridden with the exact fp32 value.
// ---------------------------------------------------------------------------
__global__ void finalize_kernel() {
    const int gi = blockIdx.x * blockDim.x + threadIdx.x;  // float4 index
    if (gi >= BATCH * DIM * (DIM / 4)) return;
    const int b = gi >> 12;
    const int rem = gi & 4095;
    const int dd = rem >> 5;
    const int e4 = rem & 31;

    float4 acc = make_float4(0.f, 0.f, 0.f, 0.f);
#pragma unroll
    for (int sp = 0; sp < SPLITS; ++sp) {
        float4 v = *(const float4*)&g_covp[sp][b][dd][e4 * 4];
        acc.x += v.x; acc.y += v.y; acc.z += v.z; acc.w += v.w;
    }
    float sd = 0.f;
    float4 se = make_float4(0.f, 0.f, 0.f, 0.f);
#pragma unroll
    for (int sp = 0; sp < SPLITS; ++sp) {
        sd += g_sums[sp][b][dd];
        float4 v = *(const float4*)&g_sums[sp][b][e4 * 4];
        se.x += v.x; se.y += v.y; se.z += v.z; se.w += v.w;
    }
    const float inv_n = 1.0f / NPTS;
    const float inv_nm1 = 1.0f / (NPTS - 1);
    const float md = sd * inv_n;
    float4 out;
    out.x = (acc.x - (float)NPTS * md * (se.x * inv_n)) * inv_nm1;
    out.y = (acc.y - (float)NPTS * md * (se.y * inv_n)) * inv_nm1;
    out.z = (acc.z - (float)NPTS * md * (se.z * inv_n)) * inv_nm1;
    out.w = (acc.w - (float)NPTS * md * (se.w * inv_n)) * inv_nm1;
    const int e0 = e4 * 4;
    if (dd >= e0 && dd < e0 + 4) {
        if (dd == e0)     out.x += LAM;
        if (dd == e0 + 1) out.y += LAM;
        if (dd == e0 + 2) out.z += LAM;
        if (dd == e0 + 3) out.w += LAM;
    }
    if (e4 == 0) {
        // exact fp32 key: (dot(col_dd, col_0) - N*m_dd*m_0)/(N-1) (+LAM if dd==0)
        float kd = 0.f;
#pragma unroll
        for (int sp = 0; sp < SPLITS; ++sp) kd += g_keyp[sp][b][dd];
        float v = (kd - (float)NPTS * md * (se.x * inv_n)) * inv_nm1;
        if (dd == 0) v += LAM;
        out.x = v;
    }
    *(float4*)&g_cov[b][dd][e4 * 4] = out;
}

// ---------------------------------------------------------------------------
// Kernel 3: lexicographic rank + gather (one block per batch)
// ---------------------------------------------------------------------------
__global__ void sort_kernel(float* __restrict__ out) {
    const int b = blockIdx.x;
    const int i = threadIdx.x;   // 0..127
    __shared__ float key0[DIM];
    __shared__ int   rank[DIM];

    const float* __restrict__ cb = &g_cov[b][0][0];
    key0[i] = cb[(size_t)i * DIM];
    __syncthreads();

    const float ki = key0[i];
    int r = 0;
    for (int j = 0; j < DIM; ++j) {
        const float kj = key0[j];
        if (kj < ki) { ++r; continue; }
        if (kj == ki && j != i) {
            bool decided = false;
            for (int c = 1; c < DIM; ++c) {
                const float aj = cb[(size_t)j * DIM + c];
                const float ai = cb[(size_t)i * DIM + c];
                if (aj != ai) { if (aj < ai) ++r; decided = true; break; }
            }
            if (!decided && j < i) ++r;
        }
    }
    rank[i] = r;
    __syncthreads();

    const float4* __restrict__ srcr = (const float4*)(cb + (size_t)i * DIM);
    float4* dstr = (float4*)(out + (size_t)b * (DIM * DIM) + (size_t)rank[i] * DIM);
#pragma unroll
    for (int c = 0; c < DIM / 4; ++c) dstr[c] = srcr[c];
}

// ---------------------------------------------------------------------------
extern "C" void kernel_launch(void* const* d_in, const int* in_sizes, int n_in,
                              void* d_out, int out_size) {
    const float* x = (const float*)d_in[0];
    float* out = (float*)d_out;

    syrk_mma_kernel<<<BATCH * SPLITS, 256>>>(x);

    const int total4 = BATCH * DIM * (DIM / 4);
    finalize_kernel<<<(total4 + 255) / 256, 256>>>();

    sort_kernel<<<BATCH, DIM>>>(out);
}